// round 1
// baseline (speedup 1.0000x reference)
#include <cuda_runtime.h>
#include <cuda_bf16.h>

// ModulatedConv3d: out[n,oc] = demod[n,oc] * conv3d(style[n,ic]*x[n,ic], weight[oc,ic,:,:,:])
// Shapes (fixed): x[4,128,16,64,64] f32, latent[4,512], weight[128,128,3,3,3],
//                 fc_w[128,512], fc_b[128]. Output [4,128,16,64,64] f32.

#define N_   4
#define IC   128
#define OC   128
#define DD   16
#define HH   64
#define WW   64
#define LAT  512
#define KV   27   // 3*3*3

__device__ float g_style[N_ * IC];
__device__ float g_demod[N_ * OC];

// ---------------------------------------------------------------------------
// Kernel 1: style[n,c] = latent[n,:] . fc_w[c,:] + fc_b[c]   (one warp per (n,c))
// ---------------------------------------------------------------------------
__global__ void style_kernel(const float* __restrict__ latent,
                             const float* __restrict__ fc_w,
                             const float* __restrict__ fc_b) {
    int warp = (blockIdx.x * blockDim.x + threadIdx.x) >> 5;
    int lane = threadIdx.x & 31;
    if (warp >= N_ * IC) return;
    int n = warp / IC;
    int c = warp - n * IC;
    const float* lrow = latent + n * LAT;
    const float* wrow = fc_w + c * LAT;
    float s = 0.f;
    #pragma unroll 4
    for (int i = lane; i < LAT; i += 32) s += lrow[i] * wrow[i];
    #pragma unroll
    for (int o = 16; o; o >>= 1) s += __shfl_xor_sync(0xFFFFFFFFu, s, o);
    if (lane == 0) g_style[n * IC + c] = s + fc_b[c];
}

// ---------------------------------------------------------------------------
// Kernel 2: demod[n,oc] = rsqrt( sum_{ic,t} (weight[oc,ic,t]*style[n,ic])^2 + 1e-8 )
// one block (256 threads) per (n, oc)
// ---------------------------------------------------------------------------
__global__ void demod_kernel(const float* __restrict__ weight) {
    int oc = blockIdx.x;
    int n  = blockIdx.y;
    const float* w = weight + oc * IC * KV;
    float s = 0.f;
    for (int i = threadIdx.x; i < IC * KV; i += 256) {
        int ic = i / KV;
        float v = w[i] * g_style[n * IC + ic];
        s += v * v;
    }
    __shared__ float red[256];
    red[threadIdx.x] = s;
    __syncthreads();
    #pragma unroll
    for (int st = 128; st; st >>= 1) {
        if (threadIdx.x < st) red[threadIdx.x] += red[threadIdx.x + st];
        __syncthreads();
    }
    if (threadIdx.x == 0) g_demod[n * OC + oc] = rsqrtf(red[0] + 1e-8f);
}

// ---------------------------------------------------------------------------
// Kernel 3: implicit-GEMM direct conv.
// Block = (h, d, n). Tile: BM=128 (all oc) x BN=64 (full W row).
// K-loop over ic; per step stage weight[:,ic,:] (128x27) and a 3x3x66 x-patch
// (pre-scaled by style[n,ic]) into smem. 256 threads, each 8 oc x 4 pix.
// Epilogue: multiply by demod[n,oc], float4 stores.
// ---------------------------------------------------------------------------
__global__ __launch_bounds__(256) void conv_kernel(const float* __restrict__ x,
                                                   const float* __restrict__ weight,
                                                   float* __restrict__ out) {
    const int h = blockIdx.x;   // 0..63
    const int d = blockIdx.y;   // 0..15
    const int n = blockIdx.z;   // 0..3

    __shared__ float Asm[OC][28];      // weight[:,ic,:], padded row (27 -> 28)
    __shared__ float patch[9][68];     // (kd*3+kh) x 66 halo row, padded to 68
    __shared__ float style_s[IC];
    __shared__ float demod_s[OC];

    const int tid = threadIdx.x;
    const int tx  = tid & 15;          // pixel group: w = tx*4 + 0..3
    const int ty  = tid >> 4;          // oc group:   oc = ty*8 + 0..7

    if (tid < IC)       style_s[tid]        = g_style[n * IC + tid];
    else                demod_s[tid - IC]   = g_demod[n * OC + (tid - IC)];
    __syncthreads();

    float acc[8][4];
    #pragma unroll
    for (int i = 0; i < 8; ++i)
        #pragma unroll
        for (int j = 0; j < 4; ++j) acc[i][j] = 0.f;

    for (int ic = 0; ic < IC; ++ic) {
        // --- stage weights for this ic: Asm[oc][t] ---
        const float* wsrc = weight + ic * KV;
        for (int i = tid; i < OC * KV; i += 256) {
            int oc_i = i / KV;
            int t    = i - oc_i * KV;
            Asm[oc_i][t] = wsrc[oc_i * (IC * KV) + t];
        }
        // --- stage x patch (3 d-planes x 3 h-rows x 66 w), scaled by style ---
        const float sc = style_s[ic];
        const float* xsrc = x + ((size_t)(n * IC + ic)) * (DD * HH * WW);
        for (int i = tid; i < 9 * 66; i += 256) {
            int r = i / 66;
            int j = i - r * 66;
            int kd = r / 3;
            int kh = r - kd * 3;
            int dz = d + kd - 1;
            int hy = h + kh - 1;
            int wx = j - 1;
            float v = 0.f;
            if ((unsigned)dz < DD && (unsigned)hy < HH && (unsigned)wx < WW)
                v = xsrc[(dz * HH + hy) * WW + wx] * sc;
            patch[r][j] = v;
        }
        __syncthreads();

        // --- compute: 27 taps x (8 oc x 4 pix) ---
        #pragma unroll
        for (int kd = 0; kd < 3; ++kd) {
            #pragma unroll
            for (int kh = 0; kh < 3; ++kh) {
                const float* prow = &patch[kd * 3 + kh][0];
                #pragma unroll
                for (int kw = 0; kw < 3; ++kw) {
                    const int t = (kd * 3 + kh) * 3 + kw;
                    const float b0 = prow[tx * 4 + kw + 0];
                    const float b1 = prow[tx * 4 + kw + 1];
                    const float b2 = prow[tx * 4 + kw + 2];
                    const float b3 = prow[tx * 4 + kw + 3];
                    #pragma unroll
                    for (int i = 0; i < 8; ++i) {
                        const float a = Asm[ty * 8 + i][t];
                        acc[i][0] += a * b0;
                        acc[i][1] += a * b1;
                        acc[i][2] += a * b2;
                        acc[i][3] += a * b3;
                    }
                }
            }
        }
        __syncthreads();
    }

    // --- epilogue: demod scale + coalesced float4 stores ---
    #pragma unroll
    for (int i = 0; i < 8; ++i) {
        const int oc = ty * 8 + i;
        const float dm = demod_s[oc];
        float4 v;
        v.x = acc[i][0] * dm;
        v.y = acc[i][1] * dm;
        v.z = acc[i][2] * dm;
        v.w = acc[i][3] * dm;
        float* dst = out + (((size_t)(n * OC + oc) * DD + d) * HH + h) * WW + tx * 4;
        *reinterpret_cast<float4*>(dst) = v;
    }
}

// ---------------------------------------------------------------------------
extern "C" void kernel_launch(void* const* d_in, const int* in_sizes, int n_in,
                              void* d_out, int out_size) {
    const float* x      = (const float*)d_in[0];   // [4,128,16,64,64]
    const float* latent = (const float*)d_in[1];   // [4,512]
    const float* weight = (const float*)d_in[2];   // [128,128,3,3,3]
    const float* fc_w   = (const float*)d_in[3];   // [128,512]
    const float* fc_b   = (const float*)d_in[4];   // [128]
    float* out = (float*)d_out;                    // [4,128,16,64,64]

    // style: 512 warps -> 64 blocks of 256 threads
    style_kernel<<<(N_ * IC) / 8, 256>>>(latent, fc_w, fc_b);
    // demod: one block per (oc, n)
    demod_kernel<<<dim3(OC, N_), 256>>>(weight);
    // conv: one block per (h, d, n) W-row
    conv_kernel<<<dim3(HH, DD, N_), 256>>>(x, weight, out);
}

// round 5
// speedup vs baseline: 5.0843x; 5.0843x over previous
#include <cuda_runtime.h>
#include <cstdint>
#include <cstddef>

#define N_   4
#define IC   128
#define OC   128
#define DD   16
#define HH   64
#define WW   64
#define LAT  512
#define KV   27
#define HW   (HH * WW)
#define DHW  (DD * HH * WW)

#define APITCH 36
#define ABUF   (OC * APITCH)    // 4608 floats per A buffer
#define PPITCH 72
#define PBUF   (12 * PPITCH)    // 864 floats per patch buffer (3 kd x 4 ph x 72)

__device__ float g_style[N_ * IC];
__device__ float g_demod[N_ * OC];
__device__ float g_wA[(size_t)N_ * IC * OC * 32];   // pre-modulated, tf32-rounded, zero-padded

__device__ __forceinline__ uint32_t smem_u32(const void* p) {
    uint32_t a;
    asm("{ .reg .u64 t; cvta.to.shared.u64 t, %1; cvt.u32.u64 %0, t; }" : "=r"(a) : "l"(p));
    return a;
}

// ---------------------------------------------------------------------------
// style[n,c] = latent[n,:] . fc_w[c,:] + fc_b[c]
// ---------------------------------------------------------------------------
__global__ void style_kernel(const float* __restrict__ latent,
                             const float* __restrict__ fc_w,
                             const float* __restrict__ fc_b) {
    int warp = (blockIdx.x * blockDim.x + threadIdx.x) >> 5;
    int lane = threadIdx.x & 31;
    if (warp >= N_ * IC) return;
    int n = warp / IC;
    int c = warp - n * IC;
    const float* lrow = latent + n * LAT;
    const float* wrow = fc_w + c * LAT;
    float s = 0.f;
    #pragma unroll 4
    for (int i = lane; i < LAT; i += 32) s += lrow[i] * wrow[i];
    #pragma unroll
    for (int o = 16; o; o >>= 1) s += __shfl_xor_sync(0xFFFFFFFFu, s, o);
    if (lane == 0) g_style[n * IC + c] = s + fc_b[c];
}

// ---------------------------------------------------------------------------
// demod[n,oc] = rsqrt( sum (w*style)^2 + 1e-8 )   (full fp32, matches reference)
// ---------------------------------------------------------------------------
__global__ void demod_kernel(const float* __restrict__ weight) {
    int oc = blockIdx.x;
    int n  = blockIdx.y;
    const float* w = weight + oc * IC * KV;
    float s = 0.f;
    for (int i = threadIdx.x; i < IC * KV; i += 256) {
        int ic = i / KV;
        float v = w[i] * g_style[n * IC + ic];
        s += v * v;
    }
    __shared__ float red[256];
    red[threadIdx.x] = s;
    __syncthreads();
    #pragma unroll
    for (int st = 128; st; st >>= 1) {
        if (threadIdx.x < st) red[threadIdx.x] += red[threadIdx.x + st];
        __syncthreads();
    }
    if (threadIdx.x == 0) g_demod[n * OC + oc] = rsqrtf(red[0] + 1e-8f);
}

// ---------------------------------------------------------------------------
// A-prep: g_wA[n][ic][oc][k<32] = tf32( weight[oc,ic,k] * style[n,ic] ), 0 for k>=27
// ---------------------------------------------------------------------------
__global__ void wprep_kernel(const float* __restrict__ weight) {
    int ic = blockIdx.x;
    int n  = blockIdx.y;
    float st = g_style[n * IC + ic];
    float* dst = g_wA + ((size_t)(n * IC + ic)) * OC * 32;
    for (int idx = threadIdx.x; idx < OC * 32; idx += 256) {
        int oc = idx >> 5, k = idx & 31;
        float v = 0.f;
        if (k < KV) v = weight[(oc * IC + ic) * KV + k] * st;
        uint32_t t;
        asm("cvt.rna.tf32.f32 %0, %1;" : "=r"(t) : "f"(v));
        dst[idx] = __uint_as_float(t);
    }
}

// ---------------------------------------------------------------------------
// Main conv: tf32 mma.sync implicit GEMM.
// Block tile: M=128 oc x N=128 pixels (2 h-rows). Warp tile 64x32.
// K: 128 ic, 32 taps each (27 real + pad). cp.async double-buffered staging.
// B fragments read directly from the halo patch (no im2col materialization).
// ---------------------------------------------------------------------------
__global__ __launch_bounds__(256, 2) void conv_mma(const float* __restrict__ x,
                                                   float* __restrict__ out) {
    __shared__ float Asm[2][ABUF];
    __shared__ float Psm[2][PBUF];
    __shared__ float demodS[OC];

    const int h0  = blockIdx.x * 2;
    const int d   = blockIdx.y;
    const int n   = blockIdx.z;
    const int tid = threadIdx.x;
    const int wid = tid >> 5;
    const int lane = tid & 31;
    const int g = lane >> 2;     // groupID 0..7
    const int c = lane & 3;      // threadInGroup 0..3
    const int wm = wid & 1;      // M half (0..1)
    const int wn = wid >> 1;     // N quarter (0..3)

    if (tid < OC) demodS[tid] = g_demod[n * OC + tid];
    for (int i = tid; i < 2 * PBUF; i += 256) (&Psm[0][0])[i] = 0.f;

    const uint32_t aBase = smem_u32(&Asm[0][0]);
    const uint32_t pBase = smem_u32(&Psm[0][0]);

    // koff[ks][half]: patch offset for tap k = ks*8 + c + 4*half; kval = real tap
    int  koff[4][2];
    bool kval[4][2];
    #pragma unroll
    for (int ks = 0; ks < 4; ++ks) {
        #pragma unroll
        for (int hlf = 0; hlf < 2; ++hlf) {
            int k = ks * 8 + c + hlf * 4;
            kval[ks][hlf] = (k < KV);
            int kk = (k < KV) ? k : 0;
            int kd = kk / 9;
            int rem = kk - kd * 9;
            int kh = rem / 3;
            int kw = rem - kh * 3;
            koff[ks][hlf] = (kd * 4 + kh) * PPITCH + kw;
        }
    }
    // pixOff[nt]: base patch offset for pixel column group (col = 3 + wcol + kw)
    int pixOff[4];
    #pragma unroll
    for (int nt = 0; nt < 4; ++nt) {
        int pix = wn * 32 + nt * 8 + g;
        pixOff[nt] = (pix >> 6) * PPITCH + 3 + (pix & 63);
    }

    float Cacc[4][4][4];
    #pragma unroll
    for (int mt = 0; mt < 4; ++mt)
        #pragma unroll
        for (int nt = 0; nt < 4; ++nt)
            #pragma unroll
            for (int r = 0; r < 4; ++r) Cacc[mt][nt][r] = 0.f;

    auto issue = [&](int ic, int buf) {
        // A tile: 16KB of pre-modulated weights, 4 x cp.async(16B) per thread
        const float4* asrc = (const float4*)(g_wA + ((size_t)(n * IC + ic)) * OC * 32);
        const uint32_t adst0 = aBase + buf * (ABUF * 4);
        #pragma unroll
        for (int i = 0; i < 4; ++i) {
            int chunk = tid + i * 256;
            int row = chunk >> 3, c4 = chunk & 7;
            uint32_t dst = adst0 + row * (APITCH * 4) + c4 * 16;
            asm volatile("cp.async.cg.shared.global [%0], [%1], 16;"
                         :: "r"(dst), "l"(asrc + chunk) : "memory");
        }
        // patch: 12 rows (3 kd x 4 ph) x 64 floats, zfill for OOB d/h rows
        if (tid < 192) {
            int r = tid >> 4, c16 = tid & 15;
            int kd = r >> 2, ph = r & 3;
            int dz = d + kd - 1, hy = h0 + ph - 1;
            bool ok = ((unsigned)dz < DD) && ((unsigned)hy < HH);
            const float* src = x + ((size_t)(n * IC + ic)) * DHW
                               + (ok ? (dz * HW + hy * WW) : 0) + c16 * 4;
            uint32_t dst = pBase + buf * (PBUF * 4) + r * (PPITCH * 4) + 16 + c16 * 16;
            int sz = ok ? 16 : 0;
            asm volatile("cp.async.cg.shared.global [%0], [%1], 16, %2;"
                         :: "r"(dst), "l"(src), "r"(sz) : "memory");
        }
    };

    __syncthreads();   // patch zeros visible before cp.async writes land

    issue(0, 0); asm volatile("cp.async.commit_group;" ::: "memory");
    issue(1, 1); asm volatile("cp.async.commit_group;" ::: "memory");

    for (int ic = 0; ic < IC; ++ic) {
        const int buf = ic & 1;
        asm volatile("cp.async.wait_group 1;" ::: "memory");
        __syncthreads();

        const float* Ab = &Asm[buf][0];
        const float* Pb = &Psm[buf][0];
        const float* aptr = Ab + (wm * 64 + g) * APITCH + c;

        #pragma unroll
        for (int ks = 0; ks < 4; ++ks) {
            uint32_t a[4][4];
            #pragma unroll
            for (int mt = 0; mt < 4; ++mt) {
                const float* p = aptr + mt * 16 * APITCH + ks * 8;
                a[mt][0] = __float_as_uint(p[0]);
                a[mt][1] = __float_as_uint(p[8 * APITCH]);
                a[mt][2] = __float_as_uint(p[4]);
                a[mt][3] = __float_as_uint(p[8 * APITCH + 4]);
            }
            #pragma unroll
            for (int nt = 0; nt < 4; ++nt) {
                uint32_t b0 = kval[ks][0] ? __float_as_uint(Pb[koff[ks][0] + pixOff[nt]]) : 0u;
                uint32_t b1 = kval[ks][1] ? __float_as_uint(Pb[koff[ks][1] + pixOff[nt]]) : 0u;
                #pragma unroll
                for (int mt = 0; mt < 4; ++mt) {
                    asm volatile(
                        "mma.sync.aligned.m16n8k8.row.col.f32.tf32.tf32.f32 "
                        "{%0,%1,%2,%3}, {%4,%5,%6,%7}, {%8,%9}, {%0,%1,%2,%3};"
                        : "+f"(Cacc[mt][nt][0]), "+f"(Cacc[mt][nt][1]),
                          "+f"(Cacc[mt][nt][2]), "+f"(Cacc[mt][nt][3])
                        : "r"(a[mt][0]), "r"(a[mt][1]), "r"(a[mt][2]), "r"(a[mt][3]),
                          "r"(b0), "r"(b1));
                }
            }
        }
        __syncthreads();
        if (ic + 2 < IC) issue(ic + 2, buf);
        asm volatile("cp.async.commit_group;" ::: "memory");
    }

    // epilogue: demod scale + float2 stores
    #pragma unroll
    for (int mt = 0; mt < 4; ++mt) {
        const int oc0 = wm * 64 + mt * 16 + g;
        const float dm0 = demodS[oc0];
        const float dm1 = demodS[oc0 + 8];
        #pragma unroll
        for (int nt = 0; nt < 4; ++nt) {
            int pix = wn * 32 + nt * 8 + c * 2;
            int hr = pix >> 6, wc = pix & 63;
            size_t o0 = ((size_t)(n * OC + oc0)) * DHW + d * HW + (h0 + hr) * WW + wc;
            float2 v0 = make_float2(Cacc[mt][nt][0] * dm0, Cacc[mt][nt][1] * dm0);
            float2 v1 = make_float2(Cacc[mt][nt][2] * dm1, Cacc[mt][nt][3] * dm1);
            *reinterpret_cast<float2*>(out + o0) = v0;
            *reinterpret_cast<float2*>(out + o0 + (size_t)8 * DHW) = v1;
        }
    }
}

// ---------------------------------------------------------------------------
extern "C" void kernel_launch(void* const* d_in, const int* in_sizes, int n_in,
                              void* d_out, int out_size) {
    const float* x      = (const float*)d_in[0];
    const float* latent = (const float*)d_in[1];
    const float* weight = (const float*)d_in[2];
    const float* fc_w   = (const float*)d_in[3];
    const float* fc_b   = (const float*)d_in[4];
    float* out = (float*)d_out;

    style_kernel<<<(N_ * IC) / 8, 256>>>(latent, fc_w, fc_b);
    demod_kernel<<<dim3(OC, N_), 256>>>(weight);
    wprep_kernel<<<dim3(IC, N_), 256>>>(weight);
    conv_mma<<<dim3(HH / 2, DD, N_), 256>>>(x, out);
}